// round 14
// baseline (speedup 1.0000x reference)
#include <cuda_runtime.h>
#include <math.h>

#define TT   1024
#define BB   32
#define CC   1024
#define KWW  3
#define NC   16      // t-chunks in fused pass
#define TC   64      // t per chunk (NC*TC == TT)
#define KSL  256     // k per staging chunk in rowgemm

// ---------------- scratch ----------------
__device__ __align__(16) float g_saq[BB * CC];          // sa(q1) [b][c]
__device__ __align__(16) float g_ker[BB * KWW * CC];    // kernels [b][w][c]
__device__ __align__(16) float g_pm[BB * NC * 4];       // per chunk: m1,m2,ws1,ws2
__device__ __align__(16) float g_pacc1[BB * NC * CC];   // chunk partial acc path1
__device__ __align__(16) float g_pacc2[BB * NC * CC];   // chunk partial acc path2
__device__ int g_cnt[BB];                                // chunk-completion counters

__device__ __forceinline__ float tanh_approx(float x) {
    float y;
    asm("tanh.approx.f32 %0, %1;" : "=f"(y) : "f"(x));
    return y;
}

// ============ kernel 1: row GEMMs, coalesced-W, warp-per-row ============
// grid 512 x 256 thr. Block = 8 rows; warp = 1 row; lane owns consecutive
// float4 of W (coalesced LDG.128). q staged per 256-k chunk in smem [b][k4]
// (conflict-free LDS.128). Butterfly reduce + bias + scatter in tail.
// Block 0 also resets the fused pass's completion counters.
__global__ void __launch_bounds__(256) k_rowgemm(
    const float* __restrict__ q1, const float* __restrict__ q2,
    const float* __restrict__ sa_w, const float* __restrict__ qk_w,
    const float* __restrict__ sa_b, const float* __restrict__ qk_b) {
    __shared__ __align__(16) float4 qs4[BB * (KSL / 4)];   // [b][k4], 32 KB

    int tid  = threadIdx.x;
    int warp = tid >> 5;
    int lane = tid & 31;

    if (blockIdx.x == 0 && tid < BB) g_cnt[tid] = 0;   // reset for this launch

    int rb = blockIdx.x;                   // 0..511
    bool is_sa = rb < 128;
    int r0 = rb * 8 + warp;                // global row (0..4095), one per warp
    int rw = is_sa ? r0 : r0 - 1024;

    const float* q = is_sa ? q1 : q2;
    const float* W = is_sa ? sa_w : qk_w;
    const float* Bi = is_sa ? sa_b : qk_b;

    const float4* wp = (const float4*)(W + (size_t)rw * CC);

    float acc[32];
#pragma unroll
    for (int b = 0; b < 32; b++) acc[b] = 0.f;

    for (int chunk = 0; chunk < 4; chunk++) {
        int k04 = chunk * (KSL / 4);
        if (chunk) __syncthreads();
#pragma unroll
        for (int i = 0; i < 8; i++) {
            int idx = i * 256 + tid;       // 0..2047
            int b   = idx >> 6;
            int kl4 = idx & 63;
            qs4[idx] = ((const float4*)q)[b * (CC / 4) + k04 + kl4];
        }
        __syncthreads();

#pragma unroll
        for (int j = 0; j < 2; j++) {
            float4 w = wp[k04 + j * 32 + lane];
#pragma unroll
            for (int b = 0; b < 32; b++) {
                float4 qv = qs4[b * 64 + j * 32 + lane];
                acc[b] = fmaf(w.x, qv.x, acc[b]);
                acc[b] = fmaf(w.y, qv.y, acc[b]);
                acc[b] = fmaf(w.z, qv.z, acc[b]);
                acc[b] = fmaf(w.w, qv.w, acc[b]);
            }
        }
    }

#pragma unroll
    for (int b = 0; b < 32; b++) {
#pragma unroll
        for (int o = 16; o > 0; o >>= 1)
            acc[b] += __shfl_xor_sync(0xffffffffu, acc[b], o);
    }

    float bias = Bi[rw];
#pragma unroll
    for (int b = 0; b < 32; b++) {
        if (lane == b) {
            float v = acc[b] + bias;
            if (is_sa) {
                g_saq[b * CC + r0] = v;
            } else {
                int rr = r0 - 1024;
                int c = rr / KWW, w = rr - c * KWW;
                g_ker[(b * KWW + w) * CC + c] = v;
            }
        }
    }
}

// ---------------- dual block reduction ----------------
__device__ __forceinline__ void bred2(float& v1, float& v2, float* sm, int sum_mode) {
    int lane = threadIdx.x & 31;
    int warp = threadIdx.x >> 5;
#pragma unroll
    for (int o = 16; o > 0; o >>= 1) {
        float o1 = __shfl_xor_sync(0xffffffffu, v1, o);
        float o2 = __shfl_xor_sync(0xffffffffu, v2, o);
        if (sum_mode) { v1 += o1; v2 += o2; }
        else          { v1 = fmaxf(v1, o1); v2 = fmaxf(v2, o2); }
    }
    if (lane == 0) { sm[warp] = v1; sm[8 + warp] = v2; }
    __syncthreads();
    float a = sm[lane & 7], b = sm[8 + (lane & 7)];
#pragma unroll
    for (int o = 4; o > 0; o >>= 1) {
        float oa = __shfl_xor_sync(0xffffffffu, a, o);
        float ob = __shfl_xor_sync(0xffffffffu, b, o);
        if (sum_mode) { a += oa; b += ob; }
        else          { a = fmaxf(a, oa); b = fmaxf(b, ob); }
    }
    v1 = __shfl_sync(0xffffffffu, a, 0);
    v2 = __shfl_sync(0xffffffffu, b, 0);
    __syncthreads();
}

// ============ kernel 2: fused flash pass + last-block combine/LN epilogue ============
// (frozen R13 winner: 88 us @ 77.7% DRAM)
__global__ void __launch_bounds__(256) k_fused(
    const float* __restrict__ k1, const float* __restrict__ k2,
    const float* __restrict__ v1, const float* __restrict__ v2,
    const float* __restrict__ a1w, const float* __restrict__ k_mask,
    const float* __restrict__ ln_g, const float* __restrict__ ln_b,
    float* __restrict__ out) {
    __shared__ __align__(16) float s_sq[CC], s_aw[CC], s_r0[CC], s_r1[CC], s_r2[CC];
    __shared__ float sA1[TC], sS0[TC], sS1[TC], sS2[TC], sW1[TC], sW2[TC];
    __shared__ float sEdge[2];
    __shared__ float sm[16];
    __shared__ float sf1[NC], sf2[NC], sS[2];
    __shared__ int s_last;

    int bid = blockIdx.x;
    int b  = bid >> 4;
    int c  = bid & (NC - 1);
    int t0 = c * TC;
    int tid = threadIdx.x;
    int warp = tid >> 5;
    int lane = tid & 31;

    {
        int i = tid;
        ((float4*)s_sq)[i] = ((const float4*)(g_saq + b * CC))[i];
        ((float4*)s_aw)[i] = ((const float4*)a1w)[i];
        ((float4*)s_r0)[i] = ((const float4*)(g_ker + (b * KWW + 0) * CC))[i];
        ((float4*)s_r1)[i] = ((const float4*)(g_ker + (b * KWW + 1) * CC))[i];
        ((float4*)s_r2)[i] = ((const float4*)(g_ker + (b * KWW + 2) * CC))[i];
    }
    __syncthreads();

    // ---- Phase A: per-row logits (warp per t) ----
#pragma unroll
    for (int it = 0; it < TC / 8; ++it) {
        int i = it * 8 + warp;
        int t = t0 + i;
        const float4* k1p = (const float4*)(k1 + (size_t)(t * BB + b) * CC);
        const float4* k2p = (const float4*)(k2 + (size_t)(t * BB + b) * CC);

        float a1 = 0.f, s0 = 0.f, s1 = 0.f, s2 = 0.f;
#pragma unroll
        for (int q = 0; q < 8; q++) {
            int c4 = q * 32 + lane;
            float4 x1 = __ldcs(k1p + c4);      // streaming: read-once data
            float4 x2 = __ldcs(k2p + c4);
            float4 sv = ((const float4*)s_sq)[c4];
            float4 av = ((const float4*)s_aw)[c4];
            float4 r0 = ((const float4*)s_r0)[c4];
            float4 r1 = ((const float4*)s_r1)[c4];
            float4 r2 = ((const float4*)s_r2)[c4];

            a1 = fmaf(tanh_approx(sv.x + x1.x), av.x, a1);
            a1 = fmaf(tanh_approx(sv.y + x1.y), av.y, a1);
            a1 = fmaf(tanh_approx(sv.z + x1.z), av.z, a1);
            a1 = fmaf(tanh_approx(sv.w + x1.w), av.w, a1);

            s0 = fmaf(r0.x, x2.x, s0); s0 = fmaf(r0.y, x2.y, s0);
            s0 = fmaf(r0.z, x2.z, s0); s0 = fmaf(r0.w, x2.w, s0);
            s1 = fmaf(r1.x, x2.x, s1); s1 = fmaf(r1.y, x2.y, s1);
            s1 = fmaf(r1.z, x2.z, s1); s1 = fmaf(r1.w, x2.w, s1);
            s2 = fmaf(r2.x, x2.x, s2); s2 = fmaf(r2.y, x2.y, s2);
            s2 = fmaf(r2.z, x2.z, s2); s2 = fmaf(r2.w, x2.w, s2);
        }
#pragma unroll
        for (int o = 16; o > 0; o >>= 1) {
            a1 += __shfl_xor_sync(0xffffffffu, a1, o);
            s0 += __shfl_xor_sync(0xffffffffu, s0, o);
            s1 += __shfl_xor_sync(0xffffffffu, s1, o);
            s2 += __shfl_xor_sync(0xffffffffu, s2, o);
        }
        if (lane == 0) { sA1[i] = a1; sS0[i] = s0; sS1[i] = s1; sS2[i] = s2; }
    }

    // boundary tap dots
    if (warp == 0) {
        float s = 0.f;
        if (t0 > 0) {
            const float4* kp = (const float4*)(k2 + (size_t)((t0 - 1) * BB + b) * CC);
#pragma unroll
            for (int q = 0; q < 8; q++) {
                int c4 = q * 32 + lane;
                float4 x = kp[c4];
                float4 r = ((const float4*)s_r0)[c4];
                s += r.x * x.x + r.y * x.y + r.z * x.z + r.w * x.w;
            }
        }
#pragma unroll
        for (int o = 16; o > 0; o >>= 1) s += __shfl_xor_sync(0xffffffffu, s, o);
        if (lane == 0) sEdge[0] = s;
    } else if (warp == 1) {
        float s = 0.f;
        if (t0 + TC < TT) {
            const float4* kp = (const float4*)(k2 + (size_t)((t0 + TC) * BB + b) * CC);
#pragma unroll
            for (int q = 0; q < 8; q++) {
                int c4 = q * 32 + lane;
                float4 x = kp[c4];
                float4 r = ((const float4*)s_r2)[c4];
                s += r.x * x.x + r.y * x.y + r.z * x.z + r.w * x.w;
            }
        }
#pragma unroll
        for (int o = 16; o > 0; o >>= 1) s += __shfl_xor_sync(0xffffffffu, s, o);
        if (lane == 0) sEdge[1] = s;
    }
    __syncthreads();

    // ---- chunk softmax stats ----
    float a1v = -3.0e38f, a2v = -3.0e38f, mk = 0.f;
    if (tid < TC) {
        int i = tid;
        a1v = sA1[i];
        a2v = sS1[i]
            + (i > 0      ? sS0[i - 1] : sEdge[0])
            + (i < TC - 1 ? sS2[i + 1] : sEdge[1]);
        mk = k_mask[(t0 + i) * BB + b];
    }
    float m1 = a1v, m2 = a2v;
    bred2(m1, m2, sm, 0);

    float w1 = 0.f, w2 = 0.f;
    if (tid < TC) {
        w1 = expf(a1v - m1) * mk;
        w2 = expf(a2v - m2) * mk;
        sW1[tid] = w1;
        sW2[tid] = w2;
    }
    float ws1 = w1, ws2 = w2;
    bred2(ws1, ws2, sm, 1);

    if (tid == 0)
        *(float4*)(g_pm + bid * 4) = make_float4(m1, m2, ws1, ws2);
    __syncthreads();

    // ---- Phase B: weighted v accumulation ----
    float4 A1 = make_float4(0.f, 0.f, 0.f, 0.f);
    float4 A2 = make_float4(0.f, 0.f, 0.f, 0.f);
#pragma unroll 4
    for (int i = 0; i < TC; i++) {
        int t = t0 + i;
        float4 xa = __ldcs(((const float4*)v1) + (size_t)(t * BB + b) * (CC / 4) + tid);
        float4 xb = __ldcs(((const float4*)v2) + (size_t)(t * BB + b) * (CC / 4) + tid);
        float u1 = sW1[i];
        float u2 = sW2[i];
        A1.x = fmaf(u1, xa.x, A1.x); A1.y = fmaf(u1, xa.y, A1.y);
        A1.z = fmaf(u1, xa.z, A1.z); A1.w = fmaf(u1, xa.w, A1.w);
        A2.x = fmaf(u2, xb.x, A2.x); A2.y = fmaf(u2, xb.y, A2.y);
        A2.z = fmaf(u2, xb.z, A2.z); A2.w = fmaf(u2, xb.w, A2.w);
    }
    ((float4*)g_pacc1)[(size_t)bid * (CC / 4) + tid] = A1;
    ((float4*)g_pacc2)[(size_t)bid * (CC / 4) + tid] = A2;

    // ---- epilogue: last block of this b performs combine + LayerNorm ----
    __threadfence();                      // publish pacc + pm before counting
    if (tid == 0) {
        int old = atomicAdd(&g_cnt[b], 1);
        s_last = (old == NC - 1);
    }
    __syncthreads();
    if (!s_last) return;

    // chunk weights (warp 0; NC == 16 <= 32 lanes)
    if (warp == 0) {
        float4 pm = make_float4(-3.0e38f, -3.0e38f, 0.f, 0.f);
        if (lane < NC) pm = *(const float4*)(g_pm + (b * NC + lane) * 4);
        float M1 = pm.x, M2 = pm.y;
#pragma unroll
        for (int o = 16; o > 0; o >>= 1) {
            M1 = fmaxf(M1, __shfl_xor_sync(0xffffffffu, M1, o));
            M2 = fmaxf(M2, __shfl_xor_sync(0xffffffffu, M2, o));
        }
        float f1 = 0.f, f2 = 0.f;
        if (lane < NC) {
            f1 = expf(pm.x - M1);
            f2 = expf(pm.y - M2);
            sf1[lane] = f1;
            sf2[lane] = f2;
        }
        float t1 = pm.z * f1, t2 = pm.w * f2;
#pragma unroll
        for (int o = 16; o > 0; o >>= 1) {
            t1 += __shfl_xor_sync(0xffffffffu, t1, o);
            t2 += __shfl_xor_sync(0xffffffffu, t2, o);
        }
        if (lane == 0) { sS[0] = t1; sS[1] = t2; }
    }
    __syncthreads();

    float i1 = 1.f / sS[0];
    float i2 = 1.f / sS[1];

    // thread owns one float4 feature slice; fixed-order chunk sum (deterministic)
    float4 x = make_float4(0.f, 0.f, 0.f, 0.f);
#pragma unroll
    for (int cc = 0; cc < NC; cc++) {
        float g1 = sf1[cc] * i1;
        float g2 = sf2[cc] * i2;
        float4 p1 = __ldcs(((const float4*)g_pacc1) + (size_t)(b * NC + cc) * (CC / 4) + tid);
        float4 p2 = __ldcs(((const float4*)g_pacc2) + (size_t)(b * NC + cc) * (CC / 4) + tid);
        x.x += g1 * p1.x + g2 * p2.x;
        x.y += g1 * p1.y + g2 * p2.y;
        x.z += g1 * p1.z + g2 * p2.z;
        x.w += g1 * p1.w + g2 * p2.w;
    }

    // LayerNorm over the 1024 features of this b
    float sv = x.x + x.y + x.z + x.w;
    float sq = x.x * x.x + x.y * x.y + x.z * x.z + x.w * x.w;
    bred2(sv, sq, sm, 1);
    float mu = sv * (1.f / (float)CC);
    float var = sq * (1.f / (float)CC) - mu * mu;
    float inv = rsqrtf(var + 1e-6f);

    int d = tid * 4;
    float4 g = *(const float4*)(ln_g + d);
    float4 bb = *(const float4*)(ln_b + d);
    float4 o;
    o.x = (x.x - mu) * inv * g.x + bb.x;
    o.y = (x.y - mu) * inv * g.y + bb.y;
    o.z = (x.z - mu) * inv * g.z + bb.z;
    o.w = (x.w - mu) * inv * g.w + bb.w;
    *(float4*)(out + b * CC + d) = o;
}

// ---------------- launch ----------------
extern "C" void kernel_launch(void* const* d_in, const int* in_sizes, int n_in,
                              void* d_out, int out_size) {
    const float* q1     = (const float*)d_in[0];
    const float* k1     = (const float*)d_in[1];
    const float* v1     = (const float*)d_in[2];
    const float* q2     = (const float*)d_in[3];
    const float* k2     = (const float*)d_in[4];
    const float* v2     = (const float*)d_in[5];
    const float* k_mask = (const float*)d_in[6];
    const float* sa_w   = (const float*)d_in[7];
    const float* sa_b   = (const float*)d_in[8];
    const float* a1_w   = (const float*)d_in[9];
    // d_in[10] = a1_b : constant shift, cancels in softmax — unused
    const float* qk_w   = (const float*)d_in[11];
    const float* qk_b   = (const float*)d_in[12];
    const float* ln_g   = (const float*)d_in[13];
    const float* ln_b   = (const float*)d_in[14];
    float* out = (float*)d_out;

    k_rowgemm<<<512, 256>>>(q1, q2, sa_w, qk_w, sa_b, qk_b);
    k_fused<<<BB * NC, 256>>>(k1, k2, v1, v2, a1_w, k_mask, ln_g, ln_b, out);
}

// round 16
// speedup vs baseline: 1.1313x; 1.1313x over previous
#include <cuda_runtime.h>
#include <math.h>

#define TT   1024
#define BB   32
#define CC   1024
#define KWW  3
#define NC   16      // t-chunks in fused pass
#define TC   64      // t per chunk (NC*TC == TT)
#define KSL  256     // k per staging chunk in rowgemm

// ---------------- scratch ----------------
__device__ __align__(16) float g_saq[BB * CC];          // sa(q1) [b][c]
__device__ __align__(16) float g_ker[BB * KWW * CC];    // kernels [b][w][c]
__device__ __align__(16) float g_pm[BB * NC * 4];       // per chunk: m1,m2,ws1,ws2
__device__ __align__(16) float g_pacc1[BB * NC * CC];   // chunk partial acc path1
__device__ __align__(16) float g_pacc2[BB * NC * CC];   // chunk partial acc path2
__device__ int g_cnt[BB];                                // chunk-completion counters

__device__ __forceinline__ float tanh_approx(float x) {
    float y;
    asm("tanh.approx.f32 %0, %1;" : "=f"(y) : "f"(x));
    return y;
}

// ============ kernel 1: row GEMMs, coalesced-W, full-K (R13 winner shape) ============
// grid 256 x 256 thr. Block = 16 rows; warp = 2 rows; lane owns consecutive
// float4 of W (coalesced LDG.128, evict-first). q staged per 256-k chunk in smem
// [b][k4] (conflict-free LDS.128). Butterfly reduce + bias + scatter in tail.
// Block 0 also resets the fused pass's completion counters.
__global__ void __launch_bounds__(256) k_rowgemm(
    const float* __restrict__ q1, const float* __restrict__ q2,
    const float* __restrict__ sa_w, const float* __restrict__ qk_w,
    const float* __restrict__ sa_b, const float* __restrict__ qk_b) {
    __shared__ __align__(16) float4 qs4[BB * (KSL / 4)];   // [b][k4], 32 KB

    int tid  = threadIdx.x;
    int warp = tid >> 5;
    int lane = tid & 31;

    if (blockIdx.x == 0 && tid < BB) g_cnt[tid] = 0;   // reset for this launch

    int rb = blockIdx.x;                   // 0..255
    bool is_sa = rb < 64;
    int r0 = rb * 16 + warp * 2;           // global row (0..4095)
    int rw = is_sa ? r0 : r0 - 1024;

    const float* q = is_sa ? q1 : q2;
    const float* W = is_sa ? sa_w : qk_w;
    const float* Bi = is_sa ? sa_b : qk_b;

    const float4* w0p = (const float4*)(W + (size_t)rw * CC);
    const float4* w1p = (const float4*)(W + (size_t)(rw + 1) * CC);

    float acc0[32], acc1[32];
#pragma unroll
    for (int b = 0; b < 32; b++) { acc0[b] = 0.f; acc1[b] = 0.f; }

    for (int chunk = 0; chunk < 4; chunk++) {
        int k04 = chunk * (KSL / 4);
        if (chunk) __syncthreads();
#pragma unroll
        for (int i = 0; i < 8; i++) {
            int idx = i * 256 + tid;       // 0..2047
            int b   = idx >> 6;
            int kl4 = idx & 63;
            qs4[idx] = ((const float4*)q)[b * (CC / 4) + k04 + kl4];
        }
        __syncthreads();

#pragma unroll
        for (int j = 0; j < 2; j++) {
            float4 w0 = __ldcs(w0p + k04 + j * 32 + lane);   // W read exactly once
            float4 w1 = __ldcs(w1p + k04 + j * 32 + lane);
#pragma unroll
            for (int b = 0; b < 32; b++) {
                float4 qv = qs4[b * 64 + j * 32 + lane];
                acc0[b] = fmaf(w0.x, qv.x, acc0[b]);
                acc0[b] = fmaf(w0.y, qv.y, acc0[b]);
                acc0[b] = fmaf(w0.z, qv.z, acc0[b]);
                acc0[b] = fmaf(w0.w, qv.w, acc0[b]);
                acc1[b] = fmaf(w1.x, qv.x, acc1[b]);
                acc1[b] = fmaf(w1.y, qv.y, acc1[b]);
                acc1[b] = fmaf(w1.z, qv.z, acc1[b]);
                acc1[b] = fmaf(w1.w, qv.w, acc1[b]);
            }
        }
    }

#pragma unroll
    for (int b = 0; b < 32; b++) {
#pragma unroll
        for (int o = 16; o > 0; o >>= 1) {
            acc0[b] += __shfl_xor_sync(0xffffffffu, acc0[b], o);
            acc1[b] += __shfl_xor_sync(0xffffffffu, acc1[b], o);
        }
    }

    float b0 = Bi[rw];
    float b1 = Bi[rw + 1];
#pragma unroll
    for (int b = 0; b < 32; b++) {
        if (lane == b) {
            float v0 = acc0[b] + b0;
            float v1 = acc1[b] + b1;
            if (is_sa) {
                g_saq[b * CC + r0]     = v0;
                g_saq[b * CC + r0 + 1] = v1;
            } else {
                int rr0 = r0 - 1024;
                int c0 = rr0 / KWW, w0i = rr0 - c0 * KWW;
                int rr1 = rr0 + 1;
                int c1 = rr1 / KWW, w1i = rr1 - c1 * KWW;
                g_ker[(b * KWW + w0i) * CC + c0] = v0;
                g_ker[(b * KWW + w1i) * CC + c1] = v1;
            }
        }
    }
}

// ---------------- dual block reduction ----------------
__device__ __forceinline__ void bred2(float& v1, float& v2, float* sm, int sum_mode) {
    int lane = threadIdx.x & 31;
    int warp = threadIdx.x >> 5;
#pragma unroll
    for (int o = 16; o > 0; o >>= 1) {
        float o1 = __shfl_xor_sync(0xffffffffu, v1, o);
        float o2 = __shfl_xor_sync(0xffffffffu, v2, o);
        if (sum_mode) { v1 += o1; v2 += o2; }
        else          { v1 = fmaxf(v1, o1); v2 = fmaxf(v2, o2); }
    }
    if (lane == 0) { sm[warp] = v1; sm[8 + warp] = v2; }
    __syncthreads();
    float a = sm[lane & 7], b = sm[8 + (lane & 7)];
#pragma unroll
    for (int o = 4; o > 0; o >>= 1) {
        float oa = __shfl_xor_sync(0xffffffffu, a, o);
        float ob = __shfl_xor_sync(0xffffffffu, b, o);
        if (sum_mode) { a += oa; b += ob; }
        else          { a = fmaxf(a, oa); b = fmaxf(b, ob); }
    }
    v1 = __shfl_sync(0xffffffffu, a, 0);
    v2 = __shfl_sync(0xffffffffu, b, 0);
    __syncthreads();
}

// ============ kernel 2: fused flash pass + last-block combine/LN epilogue ============
// (frozen R13 winner: 88 us @ 77.7% DRAM)
__global__ void __launch_bounds__(256) k_fused(
    const float* __restrict__ k1, const float* __restrict__ k2,
    const float* __restrict__ v1, const float* __restrict__ v2,
    const float* __restrict__ a1w, const float* __restrict__ k_mask,
    const float* __restrict__ ln_g, const float* __restrict__ ln_b,
    float* __restrict__ out) {
    __shared__ __align__(16) float s_sq[CC], s_aw[CC], s_r0[CC], s_r1[CC], s_r2[CC];
    __shared__ float sA1[TC], sS0[TC], sS1[TC], sS2[TC], sW1[TC], sW2[TC];
    __shared__ float sEdge[2];
    __shared__ float sm[16];
    __shared__ float sf1[NC], sf2[NC], sS[2];
    __shared__ int s_last;

    int bid = blockIdx.x;
    int b  = bid >> 4;
    int c  = bid & (NC - 1);
    int t0 = c * TC;
    int tid = threadIdx.x;
    int warp = tid >> 5;
    int lane = tid & 31;

    {
        int i = tid;
        ((float4*)s_sq)[i] = ((const float4*)(g_saq + b * CC))[i];
        ((float4*)s_aw)[i] = ((const float4*)a1w)[i];
        ((float4*)s_r0)[i] = ((const float4*)(g_ker + (b * KWW + 0) * CC))[i];
        ((float4*)s_r1)[i] = ((const float4*)(g_ker + (b * KWW + 1) * CC))[i];
        ((float4*)s_r2)[i] = ((const float4*)(g_ker + (b * KWW + 2) * CC))[i];
    }
    __syncthreads();

    // ---- Phase A: per-row logits (warp per t) ----
#pragma unroll
    for (int it = 0; it < TC / 8; ++it) {
        int i = it * 8 + warp;
        int t = t0 + i;
        const float4* k1p = (const float4*)(k1 + (size_t)(t * BB + b) * CC);
        const float4* k2p = (const float4*)(k2 + (size_t)(t * BB + b) * CC);

        float a1 = 0.f, s0 = 0.f, s1 = 0.f, s2 = 0.f;
#pragma unroll
        for (int q = 0; q < 8; q++) {
            int c4 = q * 32 + lane;
            float4 x1 = __ldcs(k1p + c4);      // streaming: read-once data
            float4 x2 = __ldcs(k2p + c4);
            float4 sv = ((const float4*)s_sq)[c4];
            float4 av = ((const float4*)s_aw)[c4];
            float4 r0 = ((const float4*)s_r0)[c4];
            float4 r1 = ((const float4*)s_r1)[c4];
            float4 r2 = ((const float4*)s_r2)[c4];

            a1 = fmaf(tanh_approx(sv.x + x1.x), av.x, a1);
            a1 = fmaf(tanh_approx(sv.y + x1.y), av.y, a1);
            a1 = fmaf(tanh_approx(sv.z + x1.z), av.z, a1);
            a1 = fmaf(tanh_approx(sv.w + x1.w), av.w, a1);

            s0 = fmaf(r0.x, x2.x, s0); s0 = fmaf(r0.y, x2.y, s0);
            s0 = fmaf(r0.z, x2.z, s0); s0 = fmaf(r0.w, x2.w, s0);
            s1 = fmaf(r1.x, x2.x, s1); s1 = fmaf(r1.y, x2.y, s1);
            s1 = fmaf(r1.z, x2.z, s1); s1 = fmaf(r1.w, x2.w, s1);
            s2 = fmaf(r2.x, x2.x, s2); s2 = fmaf(r2.y, x2.y, s2);
            s2 = fmaf(r2.z, x2.z, s2); s2 = fmaf(r2.w, x2.w, s2);
        }
#pragma unroll
        for (int o = 16; o > 0; o >>= 1) {
            a1 += __shfl_xor_sync(0xffffffffu, a1, o);
            s0 += __shfl_xor_sync(0xffffffffu, s0, o);
            s1 += __shfl_xor_sync(0xffffffffu, s1, o);
            s2 += __shfl_xor_sync(0xffffffffu, s2, o);
        }
        if (lane == 0) { sA1[i] = a1; sS0[i] = s0; sS1[i] = s1; sS2[i] = s2; }
    }

    // boundary tap dots
    if (warp == 0) {
        float s = 0.f;
        if (t0 > 0) {
            const float4* kp = (const float4*)(k2 + (size_t)((t0 - 1) * BB + b) * CC);
#pragma unroll
            for (int q = 0; q < 8; q++) {
                int c4 = q * 32 + lane;
                float4 x = kp[c4];
                float4 r = ((const float4*)s_r0)[c4];
                s += r.x * x.x + r.y * x.y + r.z * x.z + r.w * x.w;
            }
        }
#pragma unroll
        for (int o = 16; o > 0; o >>= 1) s += __shfl_xor_sync(0xffffffffu, s, o);
        if (lane == 0) sEdge[0] = s;
    } else if (warp == 1) {
        float s = 0.f;
        if (t0 + TC < TT) {
            const float4* kp = (const float4*)(k2 + (size_t)((t0 + TC) * BB + b) * CC);
#pragma unroll
            for (int q = 0; q < 8; q++) {
                int c4 = q * 32 + lane;
                float4 x = kp[c4];
                float4 r = ((const float4*)s_r2)[c4];
                s += r.x * x.x + r.y * x.y + r.z * x.z + r.w * x.w;
            }
        }
#pragma unroll
        for (int o = 16; o > 0; o >>= 1) s += __shfl_xor_sync(0xffffffffu, s, o);
        if (lane == 0) sEdge[1] = s;
    }
    __syncthreads();

    // ---- chunk softmax stats ----
    float a1v = -3.0e38f, a2v = -3.0e38f, mk = 0.f;
    if (tid < TC) {
        int i = tid;
        a1v = sA1[i];
        a2v = sS1[i]
            + (i > 0      ? sS0[i - 1] : sEdge[0])
            + (i < TC - 1 ? sS2[i + 1] : sEdge[1]);
        mk = k_mask[(t0 + i) * BB + b];
    }
    float m1 = a1v, m2 = a2v;
    bred2(m1, m2, sm, 0);

    float w1 = 0.f, w2 = 0.f;
    if (tid < TC) {
        w1 = expf(a1v - m1) * mk;
        w2 = expf(a2v - m2) * mk;
        sW1[tid] = w1;
        sW2[tid] = w2;
    }
    float ws1 = w1, ws2 = w2;
    bred2(ws1, ws2, sm, 1);

    if (tid == 0)
        *(float4*)(g_pm + bid * 4) = make_float4(m1, m2, ws1, ws2);
    __syncthreads();

    // ---- Phase B: weighted v accumulation ----
    float4 A1 = make_float4(0.f, 0.f, 0.f, 0.f);
    float4 A2 = make_float4(0.f, 0.f, 0.f, 0.f);
#pragma unroll 4
    for (int i = 0; i < TC; i++) {
        int t = t0 + i;
        float4 xa = __ldcs(((const float4*)v1) + (size_t)(t * BB + b) * (CC / 4) + tid);
        float4 xb = __ldcs(((const float4*)v2) + (size_t)(t * BB + b) * (CC / 4) + tid);
        float u1 = sW1[i];
        float u2 = sW2[i];
        A1.x = fmaf(u1, xa.x, A1.x); A1.y = fmaf(u1, xa.y, A1.y);
        A1.z = fmaf(u1, xa.z, A1.z); A1.w = fmaf(u1, xa.w, A1.w);
        A2.x = fmaf(u2, xb.x, A2.x); A2.y = fmaf(u2, xb.y, A2.y);
        A2.z = fmaf(u2, xb.z, A2.z); A2.w = fmaf(u2, xb.w, A2.w);
    }
    ((float4*)g_pacc1)[(size_t)bid * (CC / 4) + tid] = A1;
    ((float4*)g_pacc2)[(size_t)bid * (CC / 4) + tid] = A2;

    // ---- epilogue: last block of this b performs combine + LayerNorm ----
    __threadfence();                      // publish pacc + pm before counting
    if (tid == 0) {
        int old = atomicAdd(&g_cnt[b], 1);
        s_last = (old == NC - 1);
    }
    __syncthreads();
    if (!s_last) return;

    // chunk weights (warp 0; NC == 16 <= 32 lanes)
    if (warp == 0) {
        float4 pm = make_float4(-3.0e38f, -3.0e38f, 0.f, 0.f);
        if (lane < NC) pm = *(const float4*)(g_pm + (b * NC + lane) * 4);
        float M1 = pm.x, M2 = pm.y;
#pragma unroll
        for (int o = 16; o > 0; o >>= 1) {
            M1 = fmaxf(M1, __shfl_xor_sync(0xffffffffu, M1, o));
            M2 = fmaxf(M2, __shfl_xor_sync(0xffffffffu, M2, o));
        }
        float f1 = 0.f, f2 = 0.f;
        if (lane < NC) {
            f1 = expf(pm.x - M1);
            f2 = expf(pm.y - M2);
            sf1[lane] = f1;
            sf2[lane] = f2;
        }
        float t1 = pm.z * f1, t2 = pm.w * f2;
#pragma unroll
        for (int o = 16; o > 0; o >>= 1) {
            t1 += __shfl_xor_sync(0xffffffffu, t1, o);
            t2 += __shfl_xor_sync(0xffffffffu, t2, o);
        }
        if (lane == 0) { sS[0] = t1; sS[1] = t2; }
    }
    __syncthreads();

    float i1 = 1.f / sS[0];
    float i2 = 1.f / sS[1];

    // thread owns one float4 feature slice; fixed-order chunk sum (deterministic)
    float4 x = make_float4(0.f, 0.f, 0.f, 0.f);
#pragma unroll
    for (int cc = 0; cc < NC; cc++) {
        float g1 = sf1[cc] * i1;
        float g2 = sf2[cc] * i2;
        float4 p1 = __ldcs(((const float4*)g_pacc1) + (size_t)(b * NC + cc) * (CC / 4) + tid);
        float4 p2 = __ldcs(((const float4*)g_pacc2) + (size_t)(b * NC + cc) * (CC / 4) + tid);
        x.x += g1 * p1.x + g2 * p2.x;
        x.y += g1 * p1.y + g2 * p2.y;
        x.z += g1 * p1.z + g2 * p2.z;
        x.w += g1 * p1.w + g2 * p2.w;
    }

    // LayerNorm over the 1024 features of this b
    float sv = x.x + x.y + x.z + x.w;
    float sq = x.x * x.x + x.y * x.y + x.z * x.z + x.w * x.w;
    bred2(sv, sq, sm, 1);
    float mu = sv * (1.f / (float)CC);
    float var = sq * (1.f / (float)CC) - mu * mu;
    float inv = rsqrtf(var + 1e-6f);

    int d = tid * 4;
    float4 g = *(const float4*)(ln_g + d);
    float4 bb = *(const float4*)(ln_b + d);
    float4 o;
    o.x = (x.x - mu) * inv * g.x + bb.x;
    o.y = (x.y - mu) * inv * g.y + bb.y;
    o.z = (x.z - mu) * inv * g.z + bb.z;
    o.w = (x.w - mu) * inv * g.w + bb.w;
    *(float4*)(out + b * CC + d) = o;
}

// ---------------- launch ----------------
extern "C" void kernel_launch(void* const* d_in, const int* in_sizes, int n_in,
                              void* d_out, int out_size) {
    const float* q1     = (const float*)d_in[0];
    const float* k1     = (const float*)d_in[1];
    const float* v1     = (const float*)d_in[2];
    const float* q2     = (const float*)d_in[3];
    const float* k2     = (const float*)d_in[4];
    const float* v2     = (const float*)d_in[5];
    const float* k_mask = (const float*)d_in[6];
    const float* sa_w   = (const float*)d_in[7];
    const float* sa_b   = (const float*)d_in[8];
    const float* a1_w   = (const float*)d_in[9];
    // d_in[10] = a1_b : constant shift, cancels in softmax — unused
    const float* qk_w   = (const float*)d_in[11];
    const float* qk_b   = (const float*)d_in[12];
    const float* ln_g   = (const float*)d_in[13];
    const float* ln_b   = (const float*)d_in[14];
    float* out = (float*)d_out;

    k_rowgemm<<<256, 256>>>(q1, q2, sa_w, qk_w, sa_b, qk_b);
    k_fused<<<BB * NC, 256>>>(k1, k2, v1, v2, a1_w, k_mask, ln_g, ln_b, out);
}